// round 1
// baseline (speedup 1.0000x reference)
#include <cuda_runtime.h>
#include <cuda_bf16.h>

#define FG_THRESH 0.5f
#define BG_THRESH 0.5f

static constexpr int M_GT = 64;      // gt boxes per image
static constexpr int BLOCK = 256;

__global__ void __launch_bounds__(BLOCK)
roihead_kernel(const float4* __restrict__ proposals,   // [B, N] of float4
               const float4* __restrict__ gt_boxes,    // [B, 64] of float4
               const float4* __restrict__ deltas,      // [B, N] of float4
               float4* __restrict__ out_decoded,       // [B, N] of float4
               float4* __restrict__ out_targets,       // [B, N] of float4
               float*  __restrict__ out_matches,       // [B, N]
               int N)
{
    __shared__ float4 s_g[M_GT];
    __shared__ float  s_area[M_GT];

    const int b = blockIdx.y;

    // Stage gt boxes for this image into shared memory
    if (threadIdx.x < M_GT) {
        float4 g = gt_boxes[b * M_GT + threadIdx.x];
        s_g[threadIdx.x] = g;
        s_area[threadIdx.x] = (g.z - g.x) * (g.w - g.y);
    }
    __syncthreads();

    const int n = blockIdx.x * BLOCK + threadIdx.x;
    if (n >= N) return;

    const long idx = (long)b * N + n;

    const float4 p = proposals[idx];
    const float area_p = (p.z - p.x) * (p.w - p.y);

    // ---- Matcher: max / argmax IoU over 64 gt boxes (first-max wins) ----
    float best_iou = -1.0f;
    int best = 0;
#pragma unroll 8
    for (int g = 0; g < M_GT; ++g) {
        const float4 gb = s_g[g];
        const float lx = fmaxf(gb.x, p.x);
        const float ly = fmaxf(gb.y, p.y);
        const float rx = fminf(gb.z, p.z);
        const float ry = fminf(gb.w, p.w);
        const float iw = fmaxf(rx - lx, 0.0f);
        const float ih = fmaxf(ry - ly, 0.0f);
        const float inter = iw * ih;
        const float iou = inter / (s_area[g] + area_p - inter);   // IEEE div, matches XLA
        if (iou > best_iou) { best_iou = iou; best = g; }
    }

    int match;
    if (best_iou < BG_THRESH)      match = -1;   // BELOW_LOW
    else if (best_iou < FG_THRESH) match = -2;   // BETWEEN (dead: BG==FG)
    else                           match = best;

    // ---- BoxCoder.encode against matched gt (clamped gather) ----
    const float aw = p.z - p.x;
    const float ah = p.w - p.y;
    const float ax = p.x + 0.5f * aw;
    const float ay = p.y + 0.5f * ah;

    const float4 mg = s_g[match < 0 ? 0 : match];
    const float gw = fmaxf(mg.z - mg.x, 1.0f);
    const float gh = fmaxf(mg.w - mg.y, 1.0f);
    const float gx = mg.x + 0.5f * gw;
    const float gy = mg.y + 0.5f * gh;

    float4 tgt;
    tgt.x = ((gx - ax) / aw) / 0.1f;
    tgt.y = ((gy - ay) / ah) / 0.1f;
    tgt.z = logf(gw / aw) / 0.2f;
    tgt.w = logf(gh / ah) / 0.2f;

    // ---- BoxCoder.decode of predicted deltas ----
    const float4 d = deltas[idx];
    const float dx = d.x * 0.1f;
    const float dy = d.y * 0.1f;
    const float dw = d.z * 0.2f;
    const float dh = d.w * 0.2f;

    const float cx = ax + dx * aw;
    const float cy = ay + dy * ah;
    const float ww = expf(dw) * aw;
    const float hh = expf(dh) * ah;

    float4 dec;
    dec.x = cx - 0.5f * ww;
    dec.y = cy - 0.5f * hh;
    dec.z = cx + 0.5f * ww;
    dec.w = cy + 0.5f * hh;

    out_decoded[idx] = dec;
    out_targets[idx] = tgt;
    out_matches[idx] = (float)match;
}

extern "C" void kernel_launch(void* const* d_in, const int* in_sizes, int n_in,
                              void* d_out, int out_size)
{
    const float4* proposals = (const float4*)d_in[0];   // [B,N,4] f32
    const float4* gt_boxes  = (const float4*)d_in[1];   // [B,64,4] f32
    const float4* deltas    = (const float4*)d_in[2];   // [B,N,4] f32

    const int B = in_sizes[1] / (M_GT * 4);             // gt elems = B*64*4
    const int N = in_sizes[0] / (B * 4);                // proposal elems = B*N*4

    float* out = (float*)d_out;
    float4* out_decoded = (float4*)out;                           // B*N*4 floats
    float4* out_targets = (float4*)(out + (long)B * N * 4);       // B*N*4 floats
    float*  out_matches = out + 2L * B * N * 4;                   // B*N floats

    dim3 grid((N + BLOCK - 1) / BLOCK, B);
    roihead_kernel<<<grid, BLOCK>>>(proposals, gt_boxes, deltas,
                                    out_decoded, out_targets, out_matches, N);
}

// round 2
// speedup vs baseline: 2.4010x; 2.4010x over previous
#include <cuda_runtime.h>
#include <cuda_bf16.h>

#define FG_THRESH 0.5f
#define BG_THRESH 0.5f

static constexpr int M_GT = 64;
static constexpr int BLOCK = 256;

__global__ void __launch_bounds__(BLOCK)
roihead_kernel(const float4* __restrict__ proposals,   // [B, N] of float4
               const float4* __restrict__ gt_boxes,    // [B, 64] of float4
               const float4* __restrict__ deltas,      // [B, N] of float4
               float4* __restrict__ out_decoded,       // [B, N] of float4
               float4* __restrict__ out_targets,       // [B, N] of float4
               float*  __restrict__ out_matches,       // [B, N]
               int N, int half)
{
    __shared__ float4 s_g[M_GT];
    __shared__ float  s_area[M_GT];

    const int b = blockIdx.y;

    if (threadIdx.x < M_GT) {
        float4 g = gt_boxes[b * M_GT + threadIdx.x];
        s_g[threadIdx.x] = g;
        s_area[threadIdx.x] = (g.z - g.x) * (g.w - g.y);
    }
    __syncthreads();

    const int n0 = blockIdx.x * BLOCK + threadIdx.x;
    if (n0 >= half) return;
    const int n1 = n0 + half;
    const bool v1 = (n1 < N);

    const long base = (long)b * N;
    const long idx0 = base + n0;
    const long idx1 = base + (v1 ? n1 : n0);

    const float4 p0 = proposals[idx0];
    const float4 p1 = proposals[idx1];
    const float areap0 = (p0.z - p0.x) * (p0.w - p0.y);
    const float areap1 = (p1.z - p1.x) * (p1.w - p1.y);

    // ---- Matcher: max/argmax IoU over 64 gt (first-max wins) ----
    float best0 = -1.0f, best1 = -1.0f;
    int bi0 = 0, bi1 = 0;
#pragma unroll 8
    for (int g = 0; g < M_GT; ++g) {
        const float4 gb = s_g[g];
        const float ag = s_area[g];

        {
            const float iw = fmaxf(fminf(gb.z, p0.z) - fmaxf(gb.x, p0.x), 0.0f);
            const float ih = fmaxf(fminf(gb.w, p0.w) - fmaxf(gb.y, p0.y), 0.0f);
            const float inter = iw * ih;
            const float iou = __fdividef(inter, (ag + areap0) - inter);
            if (iou > best0) { best0 = iou; bi0 = g; }
        }
        {
            const float iw = fmaxf(fminf(gb.z, p1.z) - fmaxf(gb.x, p1.x), 0.0f);
            const float ih = fmaxf(fminf(gb.w, p1.w) - fmaxf(gb.y, p1.y), 0.0f);
            const float inter = iw * ih;
            const float iou = __fdividef(inter, (ag + areap1) - inter);
            if (iou > best1) { best1 = iou; bi1 = g; }
        }
    }

    // ---- Encode + decode epilogue per proposal ----
#pragma unroll
    for (int k = 0; k < 2; ++k) {
        const float4 p  = k ? p1 : p0;
        const float best = k ? best1 : best0;
        const int   bi   = k ? bi1 : bi0;
        const long  idx  = k ? idx1 : idx0;
        if (k && !v1) break;

        int match;
        if (best < BG_THRESH)      match = -1;
        else if (best < FG_THRESH) match = -2;
        else                       match = bi;

        const float aw = p.z - p.x;
        const float ah = p.w - p.y;
        const float ax = p.x + 0.5f * aw;
        const float ay = p.y + 0.5f * ah;
        const float raw = __fdividef(1.0f, aw);
        const float rah = __fdividef(1.0f, ah);

        const float4 mg = s_g[match < 0 ? 0 : match];
        const float gw = fmaxf(mg.z - mg.x, 1.0f);
        const float gh = fmaxf(mg.w - mg.y, 1.0f);
        const float gx = mg.x + 0.5f * gw;
        const float gy = mg.y + 0.5f * gh;

        float4 tgt;
        tgt.x = (gx - ax) * raw * 10.0f;
        tgt.y = (gy - ay) * rah * 10.0f;
        tgt.z = __logf(gw * raw) * 5.0f;
        tgt.w = __logf(gh * rah) * 5.0f;

        const float4 d = deltas[idx];
        const float cx = ax + (d.x * 0.1f) * aw;
        const float cy = ay + (d.y * 0.1f) * ah;
        const float ww = __expf(d.z * 0.2f) * aw;
        const float hh = __expf(d.w * 0.2f) * ah;

        float4 dec;
        dec.x = cx - 0.5f * ww;
        dec.y = cy - 0.5f * hh;
        dec.z = cx + 0.5f * ww;
        dec.w = cy + 0.5f * hh;

        out_decoded[idx] = dec;
        out_targets[idx] = tgt;
        out_matches[idx] = (float)match;
    }
}

extern "C" void kernel_launch(void* const* d_in, const int* in_sizes, int n_in,
                              void* d_out, int out_size)
{
    const float4* proposals = (const float4*)d_in[0];
    const float4* gt_boxes  = (const float4*)d_in[1];
    const float4* deltas    = (const float4*)d_in[2];

    const int B = in_sizes[1] / (M_GT * 4);
    const int N = in_sizes[0] / (B * 4);
    const int half = (N + 1) / 2;

    float* out = (float*)d_out;
    float4* out_decoded = (float4*)out;
    float4* out_targets = (float4*)(out + (long)B * N * 4);
    float*  out_matches = out + 2L * B * N * 4;

    dim3 grid((half + BLOCK - 1) / BLOCK, B);
    roihead_kernel<<<grid, BLOCK>>>(proposals, gt_boxes, deltas,
                                    out_decoded, out_targets, out_matches, N, half);
}